// round 11
// baseline (speedup 1.0000x reference)
#include <cuda_runtime.h>

// DihedralToCartesian R11: R10 structure, with the phase-1 normalization
// reassociated OFF the serial chain front. Carry raw u, raw v, jv = 1/|v|.
//   n_unit = (u x v) * (iu*jv*ISk),  m_unit = (u x (u x v)) * (iu^2*jv*ISk)
//   u' = -(CA*iu)*u + (r1*ISk*jv*iu^2)*(u x (u x v)) + (r2*ISk*jv*iu)*(u x v)
// dot+rsqrt now overlaps the crosses: chain ~60 -> ~48 cyc/step.
// True rsqrt every step -> same stability/accuracy as R9/R10.

#define TPB    96
#define NRES   126
#define CHAINS 16
#define SEG    6
#define LSEG   21             // 21 % 3 == 0 -> canonical entry frame valid

__device__ __forceinline__ float frsqrt(float x) {
    float y;
    asm("rsqrt.approx.f32 %0, %1;" : "=f"(y) : "f"(x));
    return y;
}

__global__ void __launch_bounds__(TPB, 7)
dihedral_kernel(const float* __restrict__ angles,
                const float* __restrict__ prev,
                float* __restrict__ out)
{
    __shared__ __align__(16) float buf[CHAINS * NRES * 3];   // 24192 B
    __shared__ float ex [CHAINS * SEG * 9];                  // exit p?, w, v
    __shared__ float rp [CHAINS * SEG * 12];                 // R cols + p

    const int tid   = threadIdx.x;
    const int c     = tid / SEG;
    const int s     = tid - c * SEG;
    const int Bbase = blockIdx.x * CHAINS;

    const float CA0 = cosf(2.028f), SA0 = sinf(2.028f), B0 = 1.329f;
    const float CA1 = cosf(2.124f), SA1 = sinf(2.124f), B1 = 1.458f;
    const float CA2 = cosf(1.941f), SA2 = sinf(1.941f), B2 = 1.523f;
    const float IS0 = 1.0f / SA0, IS1 = 1.0f / SA1, IS2 = 1.0f / SA2;

    // ---- phase 0: vectorized load + angle normalization (parallel) ----
    const float* gang = angles + (size_t)Bbase * (2 * NRES);
    #define PAIR(p) do {                                                        \
        int cc = (p) / (NRES / 2);                                              \
        int pj = (p) - cc * (NRES / 2);                                         \
        int j0 = pj * 2;                                                        \
        float2 s2 = *(const float2*)(gang + cc * (2 * NRES) + j0);              \
        float2 c2 = *(const float2*)(gang + cc * (2 * NRES) + NRES + j0);       \
        int k0 = j0 % 3;                                                        \
        float sa0 = (k0 == 0) ? SA0 : (k0 == 1) ? SA1 : SA2;                    \
        float sa1 = (k0 == 0) ? SA1 : (k0 == 1) ? SA2 : SA0;                    \
        float t0 = sa0 * frsqrt(fmaf(s2.x, s2.x, fmaf(c2.x, c2.x, 1e-8f)));     \
        float t1 = sa1 * frsqrt(fmaf(s2.y, s2.y, fmaf(c2.y, c2.y, 1e-8f)));     \
        int e0 = (cc * NRES + j0) * 3;                                          \
        buf[e0 + 0] =  t0 * c2.x;                                               \
        buf[e0 + 1] = -t0 * s2.x;                                               \
        buf[e0 + 3] =  t1 * c2.y;                                               \
        buf[e0 + 4] = -t1 * s2.y;                                               \
    } while (0)
    #pragma unroll
    for (int i = 0; i < 10; ++i)
        PAIR(tid + i * TPB);
    if (tid < 48)
        PAIR(tid + 960);
    #undef PAIR
    __syncthreads();

    // ---- phase 1: LSEG serial steps; raw-u/raw-v state, jv = 1/|v| ----
    float* rec = &buf[(c * NRES + s * LSEG) * 3];
    float px, py, pz;
    float ux, uy, uz;          // current bond dir, raw
    float vx, vy, vz;          // previous bond dir, raw
    float jv;                  // 1/|v|

    #define STEP(j, CAk, Bk, ISk) do {                                          \
        float r1 = rec[(j) * 3 + 0], r2 = rec[(j) * 3 + 1];                     \
        float pre = (ISk) * jv;                                                 \
        float p1 = r1 * pre, p2 = r2 * pre;                                     \
        float d  = fmaf(ux, ux, fmaf(uy, uy, uz * uz));                         \
        float ju = frsqrt(d);                                                   \
        float c1x = uy * vz - uz * vy;                                          \
        float c1y = uz * vx - ux * vz;                                          \
        float c1z = ux * vy - uy * vx;                                          \
        float c2x = uy * c1z - uz * c1y;                                        \
        float c2y = uz * c1x - ux * c1z;                                        \
        float c2z = ux * c1y - uy * c1x;                                        \
        float ju2 = ju * ju;                                                    \
        float s3 = -(CAk) * ju;                                                 \
        float s2 = p1 * ju2;                                                    \
        float s1 = p2 * ju;                                                     \
        float nux = fmaf(s3, ux, fmaf(s2, c2x, s1 * c1x));                      \
        float nuy = fmaf(s3, uy, fmaf(s2, c2y, s1 * c1y));                      \
        float nuz = fmaf(s3, uz, fmaf(s2, c2z, s1 * c1z));                      \
        px = fmaf((Bk), nux, px);                                               \
        py = fmaf((Bk), nuy, py);                                               \
        pz = fmaf((Bk), nuz, pz);                                               \
        rec[(j) * 3 + 0] = px;                                                  \
        rec[(j) * 3 + 1] = py;                                                  \
        rec[(j) * 3 + 2] = pz;                                                  \
        vx = ux; vy = uy; vz = uz; jv = ju;                                     \
        ux = nux; uy = nuy; uz = nuz;                                           \
    } while (0)

    if (s == 0) {
        // real geometry from prev_three; reference-faithful first step
        const float* pp = prev + (size_t)(Bbase + c) * 9;
        float ax = pp[0], ay = pp[1], az = pp[2];
        float bx = pp[3], by = pp[4], bz = pp[5];
        px = pp[6]; py = pp[7]; pz = pp[8];

        float r1 = rec[0], r2 = rec[1];

        float bcx = (bx - px) + 1e-8f;
        float bcy = (by - py) + 1e-8f;
        float bcz = (bz - pz) + 1e-8f;
        float ib = frsqrt(fmaf(bcx, bcx, fmaf(bcy, bcy, bcz * bcz)));
        bcx *= ib; bcy *= ib; bcz *= ib;

        float qx = bx - ax, qy = by - ay, qz = bz - az;
        float nx = fmaf(qy, bcz, fmaf(-qz, bcy, 1e-8f));
        float ny = fmaf(qz, bcx, fmaf(-qx, bcz, 1e-8f));
        float nz = fmaf(qx, bcy, fmaf(-qy, bcx, 1e-8f));
        float in_ = frsqrt(fmaf(nx, nx, fmaf(ny, ny, nz * nz)));
        nx *= in_; ny *= in_; nz *= in_;

        float mx = ny * bcz - nz * bcy;
        float my = nz * bcx - nx * bcz;
        float mz = nx * bcy - ny * bcx;

        ux = fmaf(CA0, bcx, fmaf(r1, mx, r2 * nx));
        uy = fmaf(CA0, bcy, fmaf(r1, my, r2 * ny));
        uz = fmaf(CA0, bcz, fmaf(r1, mz, r2 * nz));

        px = fmaf(B0, ux, px);
        py = fmaf(B0, uy, py);
        pz = fmaf(B0, uz, pz);
        rec[0] = px; rec[1] = py; rec[2] = pz;

        vx = -bcx; vy = -bcy; vz = -bcz;   // unit
        jv = 1.0f;
    } else {
        // canonical entry frame (boundary geometry constant: i0 % 3 == 0)
        px = 0.f; py = 0.f; pz = 0.f;
        ux = 1.f; uy = 0.f; uz = 0.f;
        vx = -CA2; vy = SA2; vz = 0.f;     // unit
        jv = 1.0f;
        STEP(0, CA0, B0, IS2);
    }
    STEP( 1, CA1, B1, IS0); STEP( 2, CA2, B2, IS1);
    #pragma unroll
    for (int m = 1; m < 7; ++m) {
        STEP(3*m + 0, CA0, B0, IS2);
        STEP(3*m + 1, CA1, B1, IS0);
        STEP(3*m + 2, CA2, B2, IS1);
    }
    #undef STEP

    {   // publish segment exit: last point + UNIT w, v for the compose
        float ju = frsqrt(fmaf(ux, ux, fmaf(uy, uy, uz * uz)));
        float* e9 = &ex[(c * SEG + s) * 9];
        e9[0] = px;      e9[1] = py;      e9[2] = pz;
        e9[3] = ux * ju; e9[4] = uy * ju; e9[5] = uz * ju;
        e9[6] = vx * jv; e9[7] = vy * jv; e9[8] = vz * jv;
    }
    __syncthreads();

    // ---- phase 2: per-chain sequential compose (16 lanes, 5 iters) ----
    if (tid < CHAINS) {
        const int cc = tid;
        float* r0 = &rp[cc * SEG * 12];
        r0[0] = 1.f; r0[1] = 0.f; r0[2] = 0.f;
        r0[3] = 0.f; r0[4] = 1.f; r0[5] = 0.f;
        r0[6] = 0.f; r0[7] = 0.f; r0[8] = 1.f;
        r0[9] = 0.f; r0[10] = 0.f; r0[11] = 0.f;

        const float* e0 = &ex[cc * SEG * 9];
        float pex = e0[0], pey = e0[1], pez = e0[2];
        float wex = e0[3], wey = e0[4], wez = e0[5];
        float vex = e0[6], vey = e0[7], vez = e0[8];

        #pragma unroll
        for (int ss = 1; ss < SEG; ++ss) {
            float d  = fmaf(vex, wex, fmaf(vey, wey, vez * wez));
            float tx = fmaf(-d, wex, vex);
            float ty = fmaf(-d, wey, vey);
            float tz = fmaf(-d, wez, vez);
            float it = frsqrt(fmaf(tx, tx, fmaf(ty, ty, fmaf(tz, tz, 1e-20f))));
            float g1x = wex,     g1y = wey,     g1z = wez;
            float g2x = tx * it, g2y = ty * it, g2z = tz * it;
            float g3x = g1y * g2z - g1z * g2y;
            float g3y = g1z * g2x - g1x * g2z;
            float g3z = g1x * g2y - g1y * g2x;

            float* rr = &rp[(cc * SEG + ss) * 12];
            rr[0] = g1x; rr[1] = g1y; rr[2] = g1z;
            rr[3] = g2x; rr[4] = g2y; rr[5] = g2z;
            rr[6] = g3x; rr[7] = g3y; rr[8] = g3z;
            rr[9] = pex; rr[10] = pey; rr[11] = pez;

            const float* es = &ex[(cc * SEG + ss) * 9];
            float qx = es[0], qy = es[1], qz = es[2];
            float wfx = es[3], wfy = es[4], wfz = es[5];
            float vfx = es[6], vfy = es[7], vfz = es[8];

            float npx = pex + qx * g1x + qy * g2x + qz * g3x;
            float npy = pey + qx * g1y + qy * g2y + qz * g3y;
            float npz = pez + qx * g1z + qy * g2z + qz * g3z;
            wex = wfx * g1x + wfy * g2x + wfz * g3x;
            wey = wfx * g1y + wfy * g2y + wfz * g3y;
            wez = wfx * g1z + wfy * g2z + wfz * g3z;
            vex = vfx * g1x + vfy * g2x + vfz * g3x;
            vey = vfx * g1y + vfy * g2y + vfz * g3y;
            vez = vfx * g1z + vfy * g2z + vfz * g3z;
            pex = npx; pey = npy; pez = npz;
        }
    }
    __syncthreads();

    // ---- phase 3: per-thread transform of own records (R in registers) ----
    {
        const float* rr = &rp[(c * SEG + s) * 12];
        float g1x = rr[0], g1y = rr[1], g1z = rr[2];
        float g2x = rr[3], g2y = rr[4], g2z = rr[5];
        float g3x = rr[6], g3y = rr[7], g3z = rr[8];
        float ppx = rr[9], ppy = rr[10], ppz = rr[11];
        #pragma unroll 3
        for (int j = 0; j < LSEG; ++j) {
            float qx = rec[j * 3 + 0];
            float qy = rec[j * 3 + 1];
            float qz = rec[j * 3 + 2];
            rec[j * 3 + 0] = fmaf(qx, g1x, fmaf(qy, g2x, fmaf(qz, g3x, ppx)));
            rec[j * 3 + 1] = fmaf(qx, g1y, fmaf(qy, g2y, fmaf(qz, g3y, ppy)));
            rec[j * 3 + 2] = fmaf(qx, g1z, fmaf(qy, g2z, fmaf(qz, g3z, ppz)));
        }
    }
    __syncthreads();

    // ---- phase 4: flat float4 copy (buf layout == global layout) ----
    {
        const float4* src = (const float4*)buf;
        float4*       dst = (float4*)(out + (size_t)Bbase * (NRES * 3));
        #pragma unroll
        for (int i = 0; i < 15; ++i)
            dst[tid + i * TPB] = src[tid + i * TPB];
        if (tid < 72)
            dst[tid + 1440] = src[tid + 1440];
    }
}

extern "C" void kernel_launch(void* const* d_in, const int* in_sizes, int n_in,
                              void* d_out, int out_size)
{
    const float* angles = (const float*)d_in[0];   // (B, 252) f32
    const float* prev   = (const float*)d_in[1];   // (B, 3, 3) f32
    float*       out    = (float*)d_out;           // (B, 126, 3) f32

    const int B = in_sizes[0] / (2 * NRES);        // 65536
    dihedral_kernel<<<B / CHAINS, TPB>>>(angles, prev, out);
}

// round 12
// speedup vs baseline: 1.1024x; 1.1024x over previous
#include <cuda_runtime.h>

// DihedralToCartesian R12: warp-self-contained chains. Each warp processes 2
// chains (half-warps of 16 lanes; 14 segments x 9 steps on lanes 0-13).
// Points kept in registers through phase 1; rigid-transform composition done
// with a Hillis-Steele scan via __shfl_up_sync(width=16) -- no __syncthreads,
// no cross-warp coupling, no serial 16-lane compose phase.
// Step math identical to R9 (analytic 1/sin(alpha) n-scale, w re-normalized
// every step; canonical entry frame valid since 9 % 3 == 0).

#define TPB    128
#define NWARP  (TPB / 32)
#define NRES   126
#define LSEG   9
#define SEGN   14

__device__ __forceinline__ float frsqrt(float x) {
    float y;
    asm("rsqrt.approx.f32 %0, %1;" : "=f"(y) : "f"(x));
    return y;
}

__global__ void __launch_bounds__(TPB, 6)
dihedral_kernel(const float* __restrict__ angles,
                const float* __restrict__ prev,
                float* __restrict__ out)
{
    // per-warp staging: 756 floats (input uses first 504; output uses all 756)
    __shared__ __align__(16) float stg[NWARP][756];

    const int lane = threadIdx.x & 31;
    const int wl   = threadIdx.x >> 5;
    const int half = lane >> 4;          // which chain of the pair
    const int s    = lane & 15;          // segment id within chain
    const bool act = (s < SEGN);

    const int chain0 = blockIdx.x * (NWARP * 2) + wl * 2;

    const float CA0 = cosf(2.028f), SA0 = sinf(2.028f), B0 = 1.329f;
    const float CA1 = cosf(2.124f), SA1 = sinf(2.124f), B1 = 1.458f;
    const float CA2 = cosf(1.941f), SA2 = sinf(1.941f), B2 = 1.523f;
    const float IS0 = 1.f / SA0, IS1 = 1.f / SA1, IS2 = 1.f / SA2;

    float* sw = stg[wl];

    // ---- phase 0: stage both chains' angle rows (504 contiguous floats) ----
    {
        const float4* src  = (const float4*)(angles + (size_t)chain0 * (2 * NRES));
        float4*       dst4 = (float4*)sw;
        #pragma unroll
        for (int r = 0; r < 4; ++r) {
            int i = lane + r * 32;
            if (i < 126) dst4[i] = src[i];
        }
    }
    __syncwarp();

    const float* msin = sw + half * 252;         // [sin 126][cos 126] per chain
    const float* mcos = msin + 126;
    const int    j0   = s * LSEG;

    // ---- phase 1: 9 serial steps, points -> registers ----
    float px, py, pz, vx, vy, vz, wx, wy, wz;
    float q[LSEG * 3];

    #define STEP(jj, CAk, Bk, ISk, SAk) do {                                    \
        float sn = msin[j0 + (jj)], co = mcos[j0 + (jj)];                       \
        float tt = (SAk) * frsqrt(fmaf(sn, sn, fmaf(co, co, 1e-8f)));           \
        float r1 = tt * co, r2 = -tt * sn;                                      \
        float nx = (wy * vz - wz * vy) * (ISk);                                 \
        float ny = (wz * vx - wx * vz) * (ISk);                                 \
        float nz = (wx * vy - wy * vx) * (ISk);                                 \
        float mx = wy * nz - wz * ny;                                           \
        float my = wz * nx - wx * nz;                                           \
        float mz = wx * ny - wy * nx;                                           \
        float ux = fmaf(-(CAk), wx, fmaf(r1, mx, r2 * nx));                     \
        float uy = fmaf(-(CAk), wy, fmaf(r1, my, r2 * ny));                     \
        float uz = fmaf(-(CAk), wz, fmaf(r1, mz, r2 * nz));                     \
        px = fmaf((Bk), ux, px);                                                \
        py = fmaf((Bk), uy, py);                                                \
        pz = fmaf((Bk), uz, pz);                                                \
        q[(jj) * 3 + 0] = px; q[(jj) * 3 + 1] = py; q[(jj) * 3 + 2] = pz;       \
        float iun = frsqrt(fmaf(ux, ux, fmaf(uy, uy, uz * uz)));                \
        vx = wx; vy = wy; vz = wz;                                              \
        wx = ux * iun; wy = uy * iun; wz = uz * iun;                            \
    } while (0)

    if (s == 0) {
        // real geometry from prev_three; reference-faithful first step
        const float* pp = prev + (size_t)(chain0 + half) * 9;
        float ax = pp[0], ay = pp[1], az = pp[2];
        float bx = pp[3], by = pp[4], bz = pp[5];
        px = pp[6]; py = pp[7]; pz = pp[8];

        float sn = msin[0], co = mcos[0];
        float tt = SA0 * frsqrt(fmaf(sn, sn, fmaf(co, co, 1e-8f)));
        float r1 = tt * co, r2 = -tt * sn;

        float bcx = (bx - px) + 1e-8f;
        float bcy = (by - py) + 1e-8f;
        float bcz = (bz - pz) + 1e-8f;
        float ib = frsqrt(fmaf(bcx, bcx, fmaf(bcy, bcy, bcz * bcz)));
        bcx *= ib; bcy *= ib; bcz *= ib;

        float qx = bx - ax, qy = by - ay, qz = bz - az;
        float nx = fmaf(qy, bcz, fmaf(-qz, bcy, 1e-8f));
        float ny = fmaf(qz, bcx, fmaf(-qx, bcz, 1e-8f));
        float nz = fmaf(qx, bcy, fmaf(-qy, bcx, 1e-8f));
        float in_ = frsqrt(fmaf(nx, nx, fmaf(ny, ny, nz * nz)));
        nx *= in_; ny *= in_; nz *= in_;

        float mx = ny * bcz - nz * bcy;
        float my = nz * bcx - nx * bcz;
        float mz = nx * bcy - ny * bcx;

        float ux = fmaf(CA0, bcx, fmaf(r1, mx, r2 * nx));
        float uy = fmaf(CA0, bcy, fmaf(r1, my, r2 * ny));
        float uz = fmaf(CA0, bcz, fmaf(r1, mz, r2 * nz));

        px = fmaf(B0, ux, px);
        py = fmaf(B0, uy, py);
        pz = fmaf(B0, uz, pz);
        q[0] = px; q[1] = py; q[2] = pz;

        float iun = frsqrt(fmaf(ux, ux, fmaf(uy, uy, uz * uz)));
        vx = -bcx; vy = -bcy; vz = -bcz;
        wx = ux * iun; wy = uy * iun; wz = uz * iun;
    } else {
        // canonical entry frame (segment boundary geometry is constant)
        px = 0.f; py = 0.f; pz = 0.f;
        wx = 1.f; wy = 0.f; wz = 0.f;
        vx = -CA2; vy = SA2; vz = 0.f;
        STEP(0, CA0, B0, IS2, SA0);
    }
    STEP(1, CA1, B1, IS0, SA1);
    STEP(2, CA2, B2, IS1, SA2);
    STEP(3, CA0, B0, IS2, SA0);
    STEP(4, CA1, B1, IS0, SA1);
    STEP(5, CA2, B2, IS1, SA2);
    STEP(6, CA0, B0, IS2, SA0);
    STEP(7, CA1, B1, IS0, SA1);
    STEP(8, CA2, B2, IS1, SA2);
    #undef STEP

    // ---- phase 2: local rigid map L_s = (GS(w, v) | p) ----
    float c1x = wx, c1y = wy, c1z = wz;
    float dvw = fmaf(vx, wx, fmaf(vy, wy, vz * wz));
    float tx = fmaf(-dvw, wx, vx);
    float ty = fmaf(-dvw, wy, vy);
    float tz = fmaf(-dvw, wz, vz);
    float it = frsqrt(fmaf(tx, tx, fmaf(ty, ty, fmaf(tz, tz, 1e-20f))));
    float c2x = tx * it, c2y = ty * it, c2z = tz * it;
    float c3x = c1y * c2z - c1z * c2y;
    float c3y = c1z * c2x - c1x * c2z;
    float c3z = c1x * c2y - c1y * c2x;
    float cpx = px, cpy = py, cpz = pz;

    // ---- inclusive Hillis-Steele scan over rigid maps (width 16) ----
    // compose(A=L from lower lane, B=current): R = A.R*B.R, p = A.R*B.p + A.p
    #pragma unroll
    for (int d = 1; d < 16; d <<= 1) {          // 1, 2, 4, 8
        float L1x = __shfl_up_sync(0xffffffffu, c1x, d, 16);
        float L1y = __shfl_up_sync(0xffffffffu, c1y, d, 16);
        float L1z = __shfl_up_sync(0xffffffffu, c1z, d, 16);
        float L2x = __shfl_up_sync(0xffffffffu, c2x, d, 16);
        float L2y = __shfl_up_sync(0xffffffffu, c2y, d, 16);
        float L2z = __shfl_up_sync(0xffffffffu, c2z, d, 16);
        float L3x = __shfl_up_sync(0xffffffffu, c3x, d, 16);
        float L3y = __shfl_up_sync(0xffffffffu, c3y, d, 16);
        float L3z = __shfl_up_sync(0xffffffffu, c3z, d, 16);
        float Lpx = __shfl_up_sync(0xffffffffu, cpx, d, 16);
        float Lpy = __shfl_up_sync(0xffffffffu, cpy, d, 16);
        float Lpz = __shfl_up_sync(0xffffffffu, cpz, d, 16);
        if (s >= d) {
            float n1x = fmaf(c1x, L1x, fmaf(c1y, L2x, c1z * L3x));
            float n1y = fmaf(c1x, L1y, fmaf(c1y, L2y, c1z * L3y));
            float n1z = fmaf(c1x, L1z, fmaf(c1y, L2z, c1z * L3z));
            float n2x = fmaf(c2x, L1x, fmaf(c2y, L2x, c2z * L3x));
            float n2y = fmaf(c2x, L1y, fmaf(c2y, L2y, c2z * L3y));
            float n2z = fmaf(c2x, L1z, fmaf(c2y, L2z, c2z * L3z));
            float n3x = fmaf(c3x, L1x, fmaf(c3y, L2x, c3z * L3x));
            float n3y = fmaf(c3x, L1y, fmaf(c3y, L2y, c3z * L3y));
            float n3z = fmaf(c3x, L1z, fmaf(c3y, L2z, c3z * L3z));
            float npx = fmaf(cpx, L1x, fmaf(cpy, L2x, fmaf(cpz, L3x, Lpx)));
            float npy = fmaf(cpx, L1y, fmaf(cpy, L2y, fmaf(cpz, L3y, Lpy)));
            float npz = fmaf(cpx, L1z, fmaf(cpy, L2z, fmaf(cpz, L3z, Lpz)));
            c1x = n1x; c1y = n1y; c1z = n1z;
            c2x = n2x; c2y = n2y; c2z = n2z;
            c3x = n3x; c3y = n3y; c3z = n3z;
            cpx = npx; cpy = npy; cpz = npz;
        }
    }

    // ---- exclusive prefix: T_s = P_{s-1}; identity at s == 0 ----
    float t1x = __shfl_up_sync(0xffffffffu, c1x, 1, 16);
    float t1y = __shfl_up_sync(0xffffffffu, c1y, 1, 16);
    float t1z = __shfl_up_sync(0xffffffffu, c1z, 1, 16);
    float t2x = __shfl_up_sync(0xffffffffu, c2x, 1, 16);
    float t2y = __shfl_up_sync(0xffffffffu, c2y, 1, 16);
    float t2z = __shfl_up_sync(0xffffffffu, c2z, 1, 16);
    float t3x = __shfl_up_sync(0xffffffffu, c3x, 1, 16);
    float t3y = __shfl_up_sync(0xffffffffu, c3y, 1, 16);
    float t3z = __shfl_up_sync(0xffffffffu, c3z, 1, 16);
    float tpx = __shfl_up_sync(0xffffffffu, cpx, 1, 16);
    float tpy = __shfl_up_sync(0xffffffffu, cpy, 1, 16);
    float tpz = __shfl_up_sync(0xffffffffu, cpz, 1, 16);
    if (s == 0) {
        t1x = 1.f; t1y = 0.f; t1z = 0.f;
        t2x = 0.f; t2y = 1.f; t2z = 0.f;
        t3x = 0.f; t3y = 0.f; t3z = 1.f;
        tpx = 0.f; tpy = 0.f; tpz = 0.f;
    }

    // ---- phase 3: transform own 9 points, stage to smem (input dead now) ----
    __syncwarp();
    if (act) {
        float* ob = sw + half * 378 + s * 27;
        #pragma unroll
        for (int jj = 0; jj < LSEG; ++jj) {
            float qx = q[jj * 3 + 0];
            float qy = q[jj * 3 + 1];
            float qz = q[jj * 3 + 2];
            ob[jj * 3 + 0] = fmaf(qx, t1x, fmaf(qy, t2x, fmaf(qz, t3x, tpx)));
            ob[jj * 3 + 1] = fmaf(qx, t1y, fmaf(qy, t2y, fmaf(qz, t3y, tpy)));
            ob[jj * 3 + 2] = fmaf(qx, t1z, fmaf(qy, t2z, fmaf(qz, t3z, tpz)));
        }
    }
    __syncwarp();

    // ---- phase 4: coalesced float4 flush (756 floats = 189 float4) ----
    {
        float4*       dst  = (float4*)(out + (size_t)chain0 * (NRES * 3));
        const float4* src4 = (const float4*)sw;
        #pragma unroll
        for (int r = 0; r < 6; ++r) {
            int i = lane + r * 32;
            if (i < 189) dst[i] = src4[i];
        }
    }
}

extern "C" void kernel_launch(void* const* d_in, const int* in_sizes, int n_in,
                              void* d_out, int out_size)
{
    const float* angles = (const float*)d_in[0];   // (B, 252) f32
    const float* prev   = (const float*)d_in[1];   // (B, 3, 3) f32
    float*       out    = (float*)d_out;           // (B, 126, 3) f32

    const int B = in_sizes[0] / (2 * NRES);        // 65536
    dihedral_kernel<<<B / (NWARP * 2), TPB>>>(angles, prev, out);
}